// round 1
// baseline (speedup 1.0000x reference)
#include <cuda_runtime.h>
#include <math.h>

#define NROWS 1048576
#define D     128
#define G     4096
#define HID   50
#define GDIM  201
#define TAILW 33
#define OUTW  (GDIM + TAILW)   // 234

// rows per block / per warp (4 warps per block, each owns a contiguous chunk)
#define RPB 2048
#define RPW (RPB / 4)

// ---------------- persistent scratch (no allocations allowed) ----------------
__device__ float g_sum [G * D];
__device__ float g_sum2[G * D];
__device__ float g_max [G * D];
__device__ float g_min [G * D];
__device__ int   g_cnt [G];

// ---------------- float atomic max/min via int ordering trick ----------------
__device__ __forceinline__ void atomicMaxF(float* a, float v) {
    if (v >= 0.0f) atomicMax((int*)a, __float_as_int(v));
    else           atomicMin((unsigned int*)a, __float_as_uint(v));
}
__device__ __forceinline__ void atomicMinF(float* a, float v) {
    if (v >= 0.0f) atomicMin((int*)a, __float_as_int(v));
    else           atomicMax((unsigned int*)a, __float_as_uint(v));
}

// ---------------- kernel 0: reset accumulators ----------------
__global__ void init_kernel() {
    int i = blockIdx.x * blockDim.x + threadIdx.x;
    if (i < G * D) {
        g_sum[i]  = 0.0f;
        g_sum2[i] = 0.0f;
        g_max[i]  = __int_as_float(0xff800000);  // -inf
        g_min[i]  = __int_as_float(0x7f800000);  // +inf
    }
    if (i < G) g_cnt[i] = 0;
}

// ---------------- kernel 1: segmented sum/sum2/max/min over x ----------------
__device__ __forceinline__ void flush_group(int g, int lane,
                                            const float4& s, const float4& s2,
                                            const float4& mx, const float4& mn,
                                            int cl) {
    int base = g * D + lane * 4;
    atomicAdd(&g_sum[base + 0], s.x);
    atomicAdd(&g_sum[base + 1], s.y);
    atomicAdd(&g_sum[base + 2], s.z);
    atomicAdd(&g_sum[base + 3], s.w);
    atomicAdd(&g_sum2[base + 0], s2.x);
    atomicAdd(&g_sum2[base + 1], s2.y);
    atomicAdd(&g_sum2[base + 2], s2.z);
    atomicAdd(&g_sum2[base + 3], s2.w);
    atomicMaxF(&g_max[base + 0], mx.x);
    atomicMaxF(&g_max[base + 1], mx.y);
    atomicMaxF(&g_max[base + 2], mx.z);
    atomicMaxF(&g_max[base + 3], mx.w);
    atomicMinF(&g_min[base + 0], mn.x);
    atomicMinF(&g_min[base + 1], mn.y);
    atomicMinF(&g_min[base + 2], mn.z);
    atomicMinF(&g_min[base + 3], mn.w);
    if (lane == 0) atomicAdd(&g_cnt[g], cl);
}

__global__ void __launch_bounds__(128, 8)
aggregate_kernel(const float* __restrict__ x, const int* __restrict__ batch) {
    int warp = threadIdx.x >> 5;
    int lane = threadIdx.x & 31;
    int r0 = blockIdx.x * RPB + warp * RPW;
    int r1 = r0 + RPW;

    const float4* __restrict__ X4 = (const float4*)x;

    float4 s  = make_float4(0.f, 0.f, 0.f, 0.f);
    float4 s2 = make_float4(0.f, 0.f, 0.f, 0.f);
    const float NEGI = __int_as_float(0xff800000);
    const float POSI = __int_as_float(0x7f800000);
    float4 mx = make_float4(NEGI, NEGI, NEGI, NEGI);
    float4 mn = make_float4(POSI, POSI, POSI, POSI);
    int cur = -1;
    int cl  = 0;

    for (int r = r0; r < r1; ++r) {
        int g = __ldg(&batch[r]);  // uniform per warp (all lanes same row)
        if (g != cur) {
            if (cur >= 0) flush_group(cur, lane, s, s2, mx, mn, cl);
            cur = g;
            s  = make_float4(0.f, 0.f, 0.f, 0.f);
            s2 = make_float4(0.f, 0.f, 0.f, 0.f);
            mx = make_float4(NEGI, NEGI, NEGI, NEGI);
            mn = make_float4(POSI, POSI, POSI, POSI);
            cl = 0;
        }
        float4 v = X4[r * 32 + lane];
        s.x += v.x; s.y += v.y; s.z += v.z; s.w += v.w;
        s2.x = fmaf(v.x, v.x, s2.x);
        s2.y = fmaf(v.y, v.y, s2.y);
        s2.z = fmaf(v.z, v.z, s2.z);
        s2.w = fmaf(v.w, v.w, s2.w);
        mx.x = fmaxf(mx.x, v.x); mx.y = fmaxf(mx.y, v.y);
        mx.z = fmaxf(mx.z, v.z); mx.w = fmaxf(mx.w, v.w);
        mn.x = fminf(mn.x, v.x); mn.y = fminf(mn.y, v.y);
        mn.z = fminf(mn.z, v.z); mn.w = fminf(mn.w, v.w);
        cl++;
    }
    if (cur >= 0) flush_group(cur, lane, s, s2, mx, mn, cl);
}

// ---------------- kernel 2: MLP + layernorm + head + tail ----------------
__global__ void __launch_bounds__(256)
finalize_kernel(const float* __restrict__ u,
                const float* __restrict__ W1, const float* __restrict__ b1,
                const float* __restrict__ ln_g, const float* __restrict__ ln_b,
                const float* __restrict__ W2, const float* __restrict__ b2,
                float* __restrict__ out) {
    int g = blockIdx.x;
    int t = threadIdx.x;

    __shared__ float aggr[4 * D];      // [mean | std | max | min]
    __shared__ float part[HID][4];
    __shared__ float hn[HID];
    __shared__ float mu_s, rstd_s;

    float c = fmaxf((float)g_cnt[g], 1.0f);

    if (t < D) {
        float s  = g_sum [g * D + t];
        float s2 = g_sum2[g * D + t];
        float mean = s / c;
        float var  = s2 / c - mean * mean;
        aggr[t]         = mean;
        aggr[D + t]     = sqrtf(fmaxf(var, 0.0f) + 1e-5f);
        aggr[2 * D + t] = g_max[g * D + t];
        aggr[3 * D + t] = g_min[g * D + t];
    }
    __syncthreads();

    // h = aggr(512) @ W1(512,50): 4 slice-partials per output
    if (t < 4 * HID) {
        int j  = t >> 2;
        int sl = t & 3;
        const float* __restrict__ w = W1 + (sl * D) * HID + j;
        const float* __restrict__ a = aggr + sl * D;
        float acc = 0.0f;
#pragma unroll 8
        for (int k = 0; k < D; ++k) acc = fmaf(a[k], w[k * HID], acc);
        part[j][sl] = acc;
    }
    __syncthreads();

    if (t < HID) {
        float hv = part[t][0] + part[t][1] + part[t][2] + part[t][3] + b1[t];
        // selu
        const float SC = 1.0507009873554804934193349852946f;
        const float AL = 1.6732632423543772848170429916717f;
        hv = (hv > 0.0f) ? SC * hv : SC * AL * expm1f(hv);
        hn[t] = hv;
    }
    __syncthreads();

    if (t == 0) {
        float m = 0.0f;
#pragma unroll
        for (int k = 0; k < HID; ++k) m += hn[k];
        m /= (float)HID;
        float v = 0.0f;
#pragma unroll
        for (int k = 0; k < HID; ++k) { float d = hn[k] - m; v = fmaf(d, d, v); }
        v /= (float)HID;
        mu_s = m;
        rstd_s = rsqrtf(v + 1e-5f);
    }
    __syncthreads();

    if (t < HID) hn[t] = (hn[t] - mu_s) * rstd_s * ln_g[t] + ln_b[t];
    __syncthreads();

    if (t < GDIM) {
        float acc = b2[t];
#pragma unroll
        for (int k = 0; k < HID; ++k) acc = fmaf(hn[k], W2[k * GDIM + t], acc);
        out[g * OUTW + t] = acc;
    } else if (t < OUTW) {
        out[g * OUTW + t] = u[g * 64 + 31 + (t - GDIM)];
    }
}

// ---------------- launch ----------------
extern "C" void kernel_launch(void* const* d_in, const int* in_sizes, int n_in,
                              void* d_out, int out_size) {
    const float* x     = (const float*)d_in[0];
    // d_in[1] edge_index, d_in[2] edge_attr: unused by the reference
    const float* u     = (const float*)d_in[3];
    const int*   batch = (const int*)d_in[4];
    const float* W1    = (const float*)d_in[5];
    const float* b1    = (const float*)d_in[6];
    const float* ln_g  = (const float*)d_in[7];
    const float* ln_b  = (const float*)d_in[8];
    const float* W2    = (const float*)d_in[9];
    const float* b2    = (const float*)d_in[10];
    float* out = (float*)d_out;

    init_kernel<<<(G * D + 255) / 256, 256>>>();
    aggregate_kernel<<<NROWS / RPB, 128>>>(x, batch);
    finalize_kernel<<<G, 256>>>(u, W1, b1, ln_g, ln_b, W2, b2, out);
}

// round 2
// speedup vs baseline: 2.0119x; 2.0119x over previous
#include <cuda_runtime.h>
#include <math.h>

#define NROWS 1048576
#define D     128
#define G     4096
#define HID   50
#define GDIM  201
#define TAILW 33
#define OUTW  (GDIM + TAILW)   // 234

// rows per block (4 warps/block, each warp owns a contiguous chunk)
#define RPB 1024
#define RPW (RPB / 4)          // 256 rows per warp
#define UNR 8                  // rows batched per iteration (MLP)

// ---------------- persistent scratch (no allocations allowed) ----------------
__device__ float g_sum [G * D];
__device__ float g_sum2[G * D];
__device__ float g_max [G * D];
__device__ float g_min [G * D];
__device__ int   g_cnt [G];

// ---------------- float atomic max/min via int ordering trick ----------------
__device__ __forceinline__ void atomicMaxF(float* a, float v) {
    if (v >= 0.0f) atomicMax((int*)a, __float_as_int(v));
    else           atomicMin((unsigned int*)a, __float_as_uint(v));
}
__device__ __forceinline__ void atomicMinF(float* a, float v) {
    if (v >= 0.0f) atomicMin((int*)a, __float_as_int(v));
    else           atomicMax((unsigned int*)a, __float_as_uint(v));
}

// ---------------- kernel 0: reset accumulators ----------------
__global__ void init_kernel() {
    int i = blockIdx.x * blockDim.x + threadIdx.x;
    if (i < G * D) {
        g_sum[i]  = 0.0f;
        g_sum2[i] = 0.0f;
        g_max[i]  = __int_as_float(0xff800000);  // -inf
        g_min[i]  = __int_as_float(0x7f800000);  // +inf
    }
    if (i < G) g_cnt[i] = 0;
}

// ---------------- kernel 1: segmented sum/sum2/max/min over x ----------------
struct Acc {
    float4 s, s2, mx, mn;
    __device__ __forceinline__ void reset() {
        s  = make_float4(0.f, 0.f, 0.f, 0.f);
        s2 = make_float4(0.f, 0.f, 0.f, 0.f);
        const float NEGI = __int_as_float(0xff800000);
        const float POSI = __int_as_float(0x7f800000);
        mx = make_float4(NEGI, NEGI, NEGI, NEGI);
        mn = make_float4(POSI, POSI, POSI, POSI);
    }
    __device__ __forceinline__ void add(const float4& v) {
        s.x += v.x; s.y += v.y; s.z += v.z; s.w += v.w;
        s2.x = fmaf(v.x, v.x, s2.x);
        s2.y = fmaf(v.y, v.y, s2.y);
        s2.z = fmaf(v.z, v.z, s2.z);
        s2.w = fmaf(v.w, v.w, s2.w);
        mx.x = fmaxf(mx.x, v.x); mx.y = fmaxf(mx.y, v.y);
        mx.z = fmaxf(mx.z, v.z); mx.w = fmaxf(mx.w, v.w);
        mn.x = fminf(mn.x, v.x); mn.y = fminf(mn.y, v.y);
        mn.z = fminf(mn.z, v.z); mn.w = fminf(mn.w, v.w);
    }
};

__device__ __forceinline__ void flush_group(int g, int lane, const Acc& a, int cl) {
    int base = g * D + lane * 4;
    atomicAdd(&g_sum[base + 0], a.s.x);
    atomicAdd(&g_sum[base + 1], a.s.y);
    atomicAdd(&g_sum[base + 2], a.s.z);
    atomicAdd(&g_sum[base + 3], a.s.w);
    atomicAdd(&g_sum2[base + 0], a.s2.x);
    atomicAdd(&g_sum2[base + 1], a.s2.y);
    atomicAdd(&g_sum2[base + 2], a.s2.z);
    atomicAdd(&g_sum2[base + 3], a.s2.w);
    atomicMaxF(&g_max[base + 0], a.mx.x);
    atomicMaxF(&g_max[base + 1], a.mx.y);
    atomicMaxF(&g_max[base + 2], a.mx.z);
    atomicMaxF(&g_max[base + 3], a.mx.w);
    atomicMinF(&g_min[base + 0], a.mn.x);
    atomicMinF(&g_min[base + 1], a.mn.y);
    atomicMinF(&g_min[base + 2], a.mn.z);
    atomicMinF(&g_min[base + 3], a.mn.w);
    if (lane == 0) atomicAdd(&g_cnt[g], cl);
}

__global__ void __launch_bounds__(128)
aggregate_kernel(const float* __restrict__ x, const int* __restrict__ batch) {
    int warp = threadIdx.x >> 5;
    int lane = threadIdx.x & 31;
    int r0 = blockIdx.x * RPB + warp * RPW;
    int r1 = r0 + RPW;

    const float4* __restrict__ X4 = (const float4*)x;

    Acc acc;
    acc.reset();
    int cur = __ldg(&batch[r0]);
    int cl  = 0;

    for (int r = r0; r < r1; r += UNR) {
        // issue ALL row loads up front (independent LDG.128s, MLP = UNR)
        float4 v[UNR];
#pragma unroll
        for (int i = 0; i < UNR; ++i)
            v[i] = X4[(r + i) * 32 + lane];

        int bfirst = __ldg(&batch[r]);
        int blast  = __ldg(&batch[r + UNR - 1]);

        if (bfirst == cur && blast == cur) {
            // fast path: whole batch in current segment (batch is sorted)
#pragma unroll
            for (int i = 0; i < UNR; ++i) acc.add(v[i]);
            cl += UNR;
        } else {
            // boundary path (~1 in 32 iterations)
#pragma unroll
            for (int i = 0; i < UNR; ++i) {
                int g = __ldg(&batch[r + i]);
                if (g != cur) {
                    flush_group(cur, lane, acc, cl);
                    acc.reset();
                    cur = g;
                    cl = 0;
                }
                acc.add(v[i]);
                cl++;
            }
        }
    }
    flush_group(cur, lane, acc, cl);
}

// ---------------- kernel 2: MLP + layernorm + head + tail ----------------
__global__ void __launch_bounds__(256)
finalize_kernel(const float* __restrict__ u,
                const float* __restrict__ W1, const float* __restrict__ b1,
                const float* __restrict__ ln_g, const float* __restrict__ ln_b,
                const float* __restrict__ W2, const float* __restrict__ b2,
                float* __restrict__ out) {
    int g = blockIdx.x;
    int t = threadIdx.x;

    __shared__ float aggr[4 * D];      // [mean | std | max | min]
    __shared__ float part[HID][4];
    __shared__ float hn[HID];
    __shared__ float mu_s, rstd_s;

    float c = fmaxf((float)g_cnt[g], 1.0f);

    if (t < D) {
        float s  = g_sum [g * D + t];
        float s2 = g_sum2[g * D + t];
        float mean = s / c;
        float var  = s2 / c - mean * mean;
        aggr[t]         = mean;
        aggr[D + t]     = sqrtf(fmaxf(var, 0.0f) + 1e-5f);
        aggr[2 * D + t] = g_max[g * D + t];
        aggr[3 * D + t] = g_min[g * D + t];
    }
    __syncthreads();

    // h = aggr(512) @ W1(512,50): 4 slice-partials per output
    if (t < 4 * HID) {
        int j  = t >> 2;
        int sl = t & 3;
        const float* __restrict__ w = W1 + (sl * D) * HID + j;
        const float* __restrict__ a = aggr + sl * D;
        float acc = 0.0f;
#pragma unroll 8
        for (int k = 0; k < D; ++k) acc = fmaf(a[k], w[k * HID], acc);
        part[j][sl] = acc;
    }
    __syncthreads();

    if (t < HID) {
        float hv = part[t][0] + part[t][1] + part[t][2] + part[t][3] + b1[t];
        // selu
        const float SC = 1.0507009873554804934193349852946f;
        const float AL = 1.6732632423543772848170429916717f;
        hv = (hv > 0.0f) ? SC * hv : SC * AL * expm1f(hv);
        hn[t] = hv;
    }
    __syncthreads();

    if (t == 0) {
        float m = 0.0f;
#pragma unroll
        for (int k = 0; k < HID; ++k) m += hn[k];
        m /= (float)HID;
        float v = 0.0f;
#pragma unroll
        for (int k = 0; k < HID; ++k) { float d = hn[k] - m; v = fmaf(d, d, v); }
        v /= (float)HID;
        mu_s = m;
        rstd_s = rsqrtf(v + 1e-5f);
    }
    __syncthreads();

    if (t < HID) hn[t] = (hn[t] - mu_s) * rstd_s * ln_g[t] + ln_b[t];
    __syncthreads();

    if (t < GDIM) {
        float acc = b2[t];
#pragma unroll
        for (int k = 0; k < HID; ++k) acc = fmaf(hn[k], W2[k * GDIM + t], acc);
        out[g * OUTW + t] = acc;
    } else if (t < OUTW) {
        out[g * OUTW + t] = u[g * 64 + 31 + (t - GDIM)];
    }
}

// ---------------- launch ----------------
extern "C" void kernel_launch(void* const* d_in, const int* in_sizes, int n_in,
                              void* d_out, int out_size) {
    const float* x     = (const float*)d_in[0];
    // d_in[1] edge_index, d_in[2] edge_attr: unused by the reference
    const float* u     = (const float*)d_in[3];
    const int*   batch = (const int*)d_in[4];
    const float* W1    = (const float*)d_in[5];
    const float* b1    = (const float*)d_in[6];
    const float* ln_g  = (const float*)d_in[7];
    const float* ln_b  = (const float*)d_in[8];
    const float* W2    = (const float*)d_in[9];
    const float* b2    = (const float*)d_in[10];
    float* out = (float*)d_out;

    init_kernel<<<(G * D + 255) / 256, 256>>>();
    aggregate_kernel<<<NROWS / RPB, 128>>>(x, batch);
    finalize_kernel<<<G, 256>>>(u, W1, b1, ln_g, ln_b, W2, b2, out);
}